// round 1
// baseline (speedup 1.0000x reference)
#include <cuda_runtime.h>
#include <math.h>

#define N_TOK   32768     // 32 * 32 * 32 tokens
#define N_CODE  8192
#define CDIM    256
#define HW      32

#define ZQ_ELEMS (32u * 256u * 32u * 32u)     // 8388608
#define OUT_LOSS  8388608
#define OUT_PERP  8388609
#define OUT_IDX   8388610
#define OUT_TOTAL (8388608 + 2 + 32768)

// ---- scratch (device globals; no allocation allowed) ----
__device__ float  g_zflat[N_TOK * CDIM];   // [token][c], 32 MB
__device__ float  g_sumz[N_TOK];
__device__ float  g_sume[N_CODE];
__device__ int    g_idx[N_TOK];
__device__ int    g_counts[N_CODE];
__device__ double g_mse;

// ============================================================
// K0: zero accumulators, compute ||e||^2 per code (fp64->fp32)
// ============================================================
__global__ void k_init(const float* __restrict__ emb) {
    int j = blockIdx.x * blockDim.x + threadIdx.x;
    if (j == 0) g_mse = 0.0;
    if (j < N_CODE) {
        g_counts[j] = 0;
        const float* r = emb + (size_t)j * CDIM;
        double s = 0.0;
        #pragma unroll 8
        for (int c = 0; c < CDIM; c++) { double v = (double)r[c]; s += v * v; }
        g_sume[j] = (float)s;
    }
}

// ============================================================
// K1: transpose z [b,c,h,w] -> z_flat [n=(b,h,w)][c], and sumz
// one block per (b,h): 32 tokens x 256 channels
// ============================================================
__global__ void k_transpose(const float* __restrict__ z) {
    __shared__ float  tile[32][257];
    __shared__ double red[8][32];
    int bh = blockIdx.x;                  // 0..1023
    int b = bh >> 5, h = bh & 31;
    int tid = threadIdx.x;
    int w = tid & 31, c0 = tid >> 5;      // c0 in 0..7

    const float* zb = z + ((size_t)b * CDIM * HW + h) * HW;  // + c*1024 + w
    double pd = 0.0;
    #pragma unroll 4
    for (int cc = 0; cc < 32; cc++) {
        int c = c0 * 32 + cc;
        float v = zb[(size_t)c * 1024 + w];
        tile[w][c] = v;
        pd += (double)v * (double)v;
    }
    red[c0][w] = pd;
    __syncthreads();

    int base = bh * 32;                   // token base
    if (tid < 32) {
        double s = 0.0;
        #pragma unroll
        for (int g = 0; g < 8; g++) s += red[g][tid];
        g_sumz[base + tid] = (float)s;
    }
    // write z_flat rows (coalesced: tid == channel)
    #pragma unroll 4
    for (int w2 = 0; w2 < 32; w2++)
        g_zflat[(size_t)(base + w2) * CDIM + tid] = tile[w2][tid];
}

// ============================================================
// K2: fused distance GEMM + argmin
// BM=128 tokens x BN=128 codes tile, BK=16, 256 threads, 8x8 micro
// ============================================================
#define BM 128
#define BN 128
#define BK 16

__global__ void __launch_bounds__(256, 2)
k_argmin(const float* __restrict__ emb, float* __restrict__ out_idx, int write_idx) {
    __shared__ float As[BK * BM];
    __shared__ float Bs[BK * BN];
    int tid = threadIdx.x;
    int tx = tid & 15, ty = tid >> 4;
    int m0 = blockIdx.x * BM;

    float bd[8]; int bj[8]; float S[8];
    #pragma unroll
    for (int i = 0; i < 8; i++) {
        bd[i] = 3.4e38f; bj[i] = 0;
        S[i] = g_sumz[m0 + ty * 8 + i];
    }

    for (int jc = 0; jc < N_CODE; jc += BN) {
        float acc[8][8];
        #pragma unroll
        for (int i = 0; i < 8; i++)
            #pragma unroll
            for (int j = 0; j < 8; j++) acc[i][j] = 0.0f;

        for (int kc = 0; kc < CDIM; kc += BK) {
            #pragma unroll
            for (int r = 0; r < 2; r++) {
                int idx4 = tid + r * 256;
                int row = idx4 >> 2, col4 = idx4 & 3;
                float4 va = *(const float4*)&g_zflat[(size_t)(m0 + row) * CDIM + kc + col4 * 4];
                float4 vb = *(const float4*)&emb[(size_t)(jc + row) * CDIM + kc + col4 * 4];
                int k0 = col4 * 4;
                As[(k0 + 0) * BM + row] = va.x; As[(k0 + 1) * BM + row] = va.y;
                As[(k0 + 2) * BM + row] = va.z; As[(k0 + 3) * BM + row] = va.w;
                Bs[(k0 + 0) * BN + row] = vb.x; Bs[(k0 + 1) * BN + row] = vb.y;
                Bs[(k0 + 2) * BN + row] = vb.z; Bs[(k0 + 3) * BN + row] = vb.w;
            }
            __syncthreads();
            #pragma unroll
            for (int k = 0; k < BK; k++) {
                float a[8], bb[8];
                *(float4*)&a[0]  = *(const float4*)&As[k * BM + ty * 8];
                *(float4*)&a[4]  = *(const float4*)&As[k * BM + ty * 8 + 4];
                *(float4*)&bb[0] = *(const float4*)&Bs[k * BN + tx * 8];
                *(float4*)&bb[4] = *(const float4*)&Bs[k * BN + tx * 8 + 4];
                #pragma unroll
                for (int i = 0; i < 8; i++)
                    #pragma unroll
                    for (int j = 0; j < 8; j++)
                        acc[i][j] = fmaf(a[i], bb[j], acc[i][j]);
            }
            __syncthreads();
        }

        // epilogue: d = fl( fl(S - 2g) + sume ), running argmin, first-index ties
        float se[8];
        #pragma unroll
        for (int j = 0; j < 8; j++) se[j] = __ldg(&g_sume[jc + tx * 8 + j]);

        #pragma unroll
        for (int i = 0; i < 8; i++) {
            float dmin = 3.4e38f; int jmin = 0x7fffffff;
            #pragma unroll
            for (int j = 0; j < 8; j++) {
                float t = fmaf(-2.0f, acc[i][j], S[i]);  // single rounding of S-2g (2g exact)
                float d = __fadd_rn(t, se[j]);
                if (d < dmin) { dmin = d; jmin = jc + tx * 8 + j; }
            }
            // reduce across the 16 lanes owning this token row
            #pragma unroll
            for (int off = 8; off; off >>= 1) {
                float d2 = __shfl_down_sync(0xffffffffu, dmin, off, 16);
                int   j2 = __shfl_down_sync(0xffffffffu, jmin, off, 16);
                if (d2 < dmin || (d2 == dmin && j2 < jmin)) { dmin = d2; jmin = j2; }
            }
            int lane = tid & 31;
            int src  = lane & 16;                 // base lane of 16-group
            dmin = __shfl_sync(0xffffffffu, dmin, src, 32);
            jmin = __shfl_sync(0xffffffffu, jmin, src, 32);
            if (dmin < bd[i] || (dmin == bd[i] && jmin < bj[i])) { bd[i] = dmin; bj[i] = jmin; }
        }
    }

    if (tx == 0) {
        #pragma unroll
        for (int i = 0; i < 8; i++) {
            int n = m0 + ty * 8 + i;
            g_idx[n] = bj[i];
            atomicAdd(&g_counts[bj[i]], 1);
            if (write_idx) out_idx[n] = (float)bj[i];
        }
    }
}

// ============================================================
// K3: gather z_q = emb[idx], write z_q_st in [b,c,h,w], mse accum
// one block per (b,h)
// ============================================================
__global__ void k_output(const float* __restrict__ z, const float* __restrict__ emb,
                         float* __restrict__ out) {
    __shared__ float  tile[32][257];
    __shared__ double red[256];
    int bh = blockIdx.x;
    int b = bh >> 5, h = bh & 31;
    int tid = threadIdx.x;
    int base = bh * 32;

    for (int w = 0; w < 32; w++) {
        int idx = g_idx[base + w];
        tile[w][tid] = emb[(size_t)idx * CDIM + tid];   // coalesced row gather
    }
    __syncthreads();

    int w = tid & 31, c0 = tid >> 5;
    const float* zb = z   + ((size_t)b * CDIM * HW + h) * HW;
    float*       ob = out + ((size_t)b * CDIM * HW + h) * HW;
    double macc = 0.0;
    #pragma unroll 4
    for (int cc = 0; cc < 32; cc++) {
        int c = c0 * 32 + cc;
        size_t off = (size_t)c * 1024 + w;
        float zv = zb[off];
        float q  = tile[w][c];
        // emulate straight-through: z + fl(z_q - z) (bitwise match with ref)
        float diff = __fsub_rn(q, zv);
        ob[off] = __fadd_rn(zv, diff);
        double e = (double)zv - (double)q;
        macc += e * e;
    }
    red[tid] = macc;
    __syncthreads();
    #pragma unroll
    for (int s = 128; s; s >>= 1) {
        if (tid < s) red[tid] += red[tid + s];
        __syncthreads();
    }
    if (tid == 0) atomicAdd(&g_mse, red[0]);
}

// ============================================================
// K4: perplexity + vq_loss scalars
// ============================================================
__global__ void k_scalars(float* __restrict__ out_scalars) {
    __shared__ double red[256];
    int tid = threadIdx.x;
    double s = 0.0;
    for (int j = tid; j < N_CODE; j += 256) {
        int c = g_counts[j];
        if (c > 0) {
            double p = (double)c / (double)N_TOK;
            s += p * log(p);
        }
    }
    red[tid] = s;
    __syncthreads();
    #pragma unroll
    for (int st = 128; st; st >>= 1) {
        if (tid < st) red[tid] += red[tid + st];
        __syncthreads();
    }
    if (tid == 0) {
        double loss = 1.25 * g_mse / (double)((size_t)N_TOK * CDIM);
        out_scalars[0] = (float)loss;
        out_scalars[1] = (float)exp(-red[0]);
    }
}

// ============================================================
extern "C" void kernel_launch(void* const* d_in, const int* in_sizes, int n_in,
                              void* d_out, int out_size) {
    const float* z   = (const float*)d_in[0];   // z_e [32,256,32,32]
    const float* emb = (const float*)d_in[1];   // emb_w [8192,256]
    float* out = (float*)d_out;

    int has_extra = (out_size >= (int)OUT_TOTAL) ? 1 : 0;

    k_init<<<(N_CODE + 255) / 256, 256>>>(emb);
    k_transpose<<<1024, 256>>>(z);
    k_argmin<<<N_TOK / BM, 256>>>(emb, out + OUT_IDX, has_extra);
    k_output<<<1024, 256>>>(z, emb, out);
    if (has_extra) k_scalars<<<1, 256>>>(out + OUT_LOSS);
}

// round 5
// speedup vs baseline: 4.1934x; 4.1934x over previous
#include <cuda_runtime.h>
#include <cuda_bf16.h>
#include <math.h>
#include <stdint.h>

#define N_TOK   32768
#define N_CODE  8192
#define CDIM    256
#define HW      32

#define OUT_LOSS  8388608
#define OUT_PERP  8388609
#define OUT_IDX   8388610
#define OUT_TOTAL (8388608 + 2 + 32768)

#define CAP   48
#define EPS   1.5e-4f

// ---------------- device scratch (no allocation allowed) ----------------
__device__ float          g_zflat[N_TOK * CDIM];      // fp32 [token][c]
__device__ __nv_bfloat16  g_zf16[N_TOK * CDIM];       // bf16 tokens
__device__ __nv_bfloat16  g_ef16[N_CODE * CDIM];      // bf16 codebook
__device__ float          g_sumz[N_TOK];
__device__ float          g_sume[N_CODE];
__device__ int            g_idx[N_TOK];
__device__ int            g_counts[N_CODE];
__device__ int            g_cand[N_TOK][CAP];
__device__ int            g_cnt[N_TOK];
__device__ double         g_mse;

// ---------------- baseline-PTX helpers (NO sm_103a-only features) ----------------
__device__ __forceinline__ uint32_t smem_u32(const void* p) {
    uint32_t a;
    asm("{ .reg .u64 t; cvta.to.shared.u64 t, %1; cvt.u32.u64 %0, t; }" : "=r"(a) : "l"(p));
    return a;
}
#define CP_ASYNC(dst, src) asm volatile("cp.async.cg.shared.global [%0], [%1], 16;" :: "r"(dst), "l"(src))
#define CP_COMMIT()        asm volatile("cp.async.commit_group;" ::: "memory")
#define CP_WAIT1()         asm volatile("cp.async.wait_group 1;" ::: "memory")
#define CP_WAIT0()         asm volatile("cp.async.wait_group 0;" ::: "memory")

#define LDSM4(r, addr) \
    asm volatile("ldmatrix.sync.aligned.m8n8.x4.shared.b16 {%0,%1,%2,%3}, [%4];" \
        : "=r"((r)[0]), "=r"((r)[1]), "=r"((r)[2]), "=r"((r)[3]) : "r"(addr))

#define MMA_BF16(d, a, b0, b1) \
    asm volatile("mma.sync.aligned.m16n8k16.row.col.f32.bf16.bf16.f32 " \
        "{%0,%1,%2,%3}, {%4,%5,%6,%7}, {%8,%9}, {%0,%1,%2,%3};" \
        : "+f"((d)[0]), "+f"((d)[1]), "+f"((d)[2]), "+f"((d)[3]) \
        : "r"((a)[0]), "r"((a)[1]), "r"((a)[2]), "r"((a)[3]), "r"(b0), "r"(b1))

// ============================================================
// K0: init accumulators, ||e||^2 (fp64->fp32)
// ============================================================
__global__ void k_init(const float* __restrict__ emb) {
    int j = blockIdx.x * blockDim.x + threadIdx.x;
    if (j == 0) g_mse = 0.0;
    if (j < N_CODE) {
        g_counts[j] = 0;
        const float* r = emb + (size_t)j * CDIM;
        double s = 0.0;
        #pragma unroll 8
        for (int c = 0; c < CDIM; c++) { double v = (double)r[c]; s += v * v; }
        g_sume[j] = (float)s;
    }
}

__global__ void k_conv_emb(const float* __restrict__ emb) {
    int i = blockIdx.x * blockDim.x + threadIdx.x;
    if (i < N_CODE * CDIM) g_ef16[i] = __float2bfloat16(emb[i]);
}

// ============================================================
// K1: transpose z -> z_flat (fp32 + bf16) + sumz
// ============================================================
__global__ void k_transpose(const float* __restrict__ z) {
    __shared__ float  tile[32][257];
    __shared__ double red[8][32];
    int bh = blockIdx.x;
    int b = bh >> 5, h = bh & 31;
    int tid = threadIdx.x;
    int w = tid & 31, c0 = tid >> 5;

    const float* zb = z + ((size_t)b * CDIM * HW + h) * HW;
    double pd = 0.0;
    #pragma unroll 4
    for (int cc = 0; cc < 32; cc++) {
        int c = c0 * 32 + cc;
        float v = zb[(size_t)c * 1024 + w];
        tile[w][c] = v;
        pd += (double)v * (double)v;
    }
    red[c0][w] = pd;
    __syncthreads();

    int base = bh * 32;
    if (tid < 32) {
        double s = 0.0;
        #pragma unroll
        for (int g = 0; g < 8; g++) s += red[g][tid];
        g_sumz[base + tid] = (float)s;
    }
    #pragma unroll 4
    for (int w2 = 0; w2 < 32; w2++) {
        float v = tile[w2][tid];
        size_t o = (size_t)(base + w2) * CDIM + tid;
        g_zflat[o] = v;
        g_zf16[o]  = __float2bfloat16(v);
    }
}

// ============================================================
// Pass A: bf16 mma.sync GEMM + streaming min + candidate capture
// CTA = 128 tokens x 8192 codes (64 tiles of 128 codes)
// SMEM: A[128][256] resident (64KB) + B double buffer (2x64KB) + scnt
// 8 warps, 2(m) x 4(n), warp tile 64x32, m16n8k16
// ============================================================
#define SM_A      0
#define SM_B0     65536
#define SM_B1     131072
#define SM_CNT    196608
#define SM_TOTAL  (196608 + 512)

__device__ __forceinline__ void load_B_tile(int t, uint32_t base, int tid) {
    const __nv_bfloat16* ep = g_ef16 + (size_t)t * 128 * CDIM;
    #pragma unroll
    for (int it = 0; it < 16; it++) {
        int idx = tid + it * 256;
        int r = idx >> 5, c = idx & 31;
        uint32_t dst = base + (uint32_t)r * 512u + (uint32_t)((c ^ (r & 7)) * 16);
        CP_ASYNC(dst, (const void*)(ep + (size_t)r * CDIM + c * 8));
    }
}

__global__ void __launch_bounds__(256, 1) k_passA() {
    extern __shared__ char smem[];
    const uint32_t sb = smem_u32(smem);
    int* scnt = (int*)(smem + SM_CNT);
    int tid = threadIdx.x, lane = tid & 31, wid = tid >> 5;
    int warp_m = wid >> 2, warp_n = wid & 3;
    int m0 = blockIdx.x * 128;

    if (tid < 128) scnt[tid] = 0;

    // stage whole A tile (128 tokens x 256) into swizzled SMEM
    {
        const __nv_bfloat16* za = g_zf16 + (size_t)m0 * CDIM;
        #pragma unroll
        for (int it = 0; it < 16; it++) {
            int idx = tid + it * 256;
            int r = idx >> 5, c = idx & 31;
            uint32_t dst = sb + SM_A + (uint32_t)r * 512u + (uint32_t)((c ^ (r & 7)) * 16);
            CP_ASYNC(dst, (const void*)(za + (size_t)r * CDIM + c * 8));
        }
    }
    CP_COMMIT();
    load_B_tile(0, sb + SM_B0, tid);
    CP_COMMIT();

    // per-thread A-row addressing (fixed across tiles)
    uint32_t a_row[4]; int a_rl[4];
    #pragma unroll
    for (int mi = 0; mi < 4; mi++) {
        int row = warp_m * 64 + mi * 16 + (lane & 15);
        a_row[mi] = sb + SM_A + (uint32_t)row * 512u;
        a_rl[mi] = row & 7;
    }
    int a_hi = (lane >> 4) & 1;
    int q = lane >> 3;
    int b_hi = q & 1;
    int b_rowoff[2]; int b_rl[2];
    #pragma unroll
    for (int p = 0; p < 2; p++) {
        int row = warp_n * 32 + p * 16 + ((q & 2) << 2) + (lane & 7);
        b_rowoff[p] = row * 512;
        b_rl[p] = row & 7;
    }

    float bd[8];
    #pragma unroll
    for (int i = 0; i < 8; i++) bd[i] = 3.4e38f;

    for (int t = 0; t < 64; t++) {
        uint32_t bbuf = sb + ((t & 1) ? SM_B1 : SM_B0);
        if (t + 1 < 64) {
            load_B_tile(t + 1, sb + ((t & 1) ? SM_B0 : SM_B1), tid);
            CP_COMMIT();
            CP_WAIT1();
        } else {
            CP_WAIT0();
        }
        __syncthreads();

        float acc[4][4][4];
        #pragma unroll
        for (int mi = 0; mi < 4; mi++)
            #pragma unroll
            for (int ni = 0; ni < 4; ni++)
                #pragma unroll
                for (int e = 0; e < 4; e++) acc[mi][ni][e] = 0.0f;

        #pragma unroll 4
        for (int ks = 0; ks < 16; ks++) {
            uint32_t a[4][4], b[2][4];
            #pragma unroll
            for (int mi = 0; mi < 4; mi++) {
                uint32_t addr = a_row[mi] + (uint32_t)((((ks * 2 + a_hi) ^ a_rl[mi])) * 16);
                LDSM4(a[mi], addr);
            }
            #pragma unroll
            for (int p = 0; p < 2; p++) {
                uint32_t addr = bbuf + (uint32_t)b_rowoff[p] + (uint32_t)((((ks * 2 + b_hi) ^ b_rl[p])) * 16);
                LDSM4(b[p], addr);
            }
            #pragma unroll
            for (int mi = 0; mi < 4; mi++) {
                MMA_BF16(acc[mi][0], a[mi], b[0][0], b[0][1]);
                MMA_BF16(acc[mi][1], a[mi], b[0][2], b[0][3]);
                MMA_BF16(acc[mi][2], a[mi], b[1][0], b[1][1]);
                MMA_BF16(acc[mi][3], a[mi], b[1][2], b[1][3]);
            }
        }

        // ---- epilogue: scores, running min, candidate capture ----
        float se[4][2];
        int colbase = t * 128 + warp_n * 32 + 2 * (lane & 3);
        #pragma unroll
        for (int ni = 0; ni < 4; ni++) {
            se[ni][0] = __ldg(&g_sume[colbase + ni * 8]);
            se[ni][1] = __ldg(&g_sume[colbase + ni * 8 + 1]);
        }
        #pragma unroll
        for (int mi = 0; mi < 4; mi++) {
            #pragma unroll
            for (int half = 0; half < 2; half++) {
                float s[8];
                #pragma unroll
                for (int ni = 0; ni < 4; ni++) {
                    s[ni * 2 + 0] = fmaf(-2.0f, acc[mi][ni][half * 2 + 0], se[ni][0]);
                    s[ni * 2 + 1] = fmaf(-2.0f, acc[mi][ni][half * 2 + 1], se[ni][1]);
                }
                float lmin = s[0];
                #pragma unroll
                for (int v = 1; v < 8; v++) lmin = fminf(lmin, s[v]);
                lmin = fminf(lmin, __shfl_xor_sync(0xffffffffu, lmin, 1));
                lmin = fminf(lmin, __shfl_xor_sync(0xffffffffu, lmin, 2));
                int bi = mi * 2 + half;
                float nm = fminf(bd[bi], lmin);
                if (lmin < bd[bi] + EPS) {
                    int r_local = warp_m * 64 + mi * 16 + half * 8 + (lane >> 2);
                    #pragma unroll
                    for (int v = 0; v < 8; v++) {
                        if (s[v] < nm + EPS) {
                            int pos = atomicAdd(&scnt[r_local], 1);
                            if (pos < CAP)
                                g_cand[m0 + r_local][pos] = colbase + (v >> 1) * 8 + (v & 1);
                        }
                    }
                }
                bd[bi] = nm;
            }
        }
        __syncthreads();
    }

    if (tid < 128) g_cnt[m0 + tid] = scnt[tid];
}

// ============================================================
// Pass B: exact fp32 (reference-rounded) re-argmin over candidates
// ============================================================
__global__ void __launch_bounds__(256) k_passB(const float* __restrict__ emb,
                                               float* __restrict__ out_idx, int write_idx) {
    __shared__ float zrow[8][CDIM];
    int wid = threadIdx.x >> 5, lane = threadIdx.x & 31;
    int n = blockIdx.x * 8 + wid;

    const float* zp = g_zflat + (size_t)n * CDIM;
    *(float4*)&zrow[wid][lane * 8]     = *(const float4*)(zp + lane * 8);
    *(float4*)&zrow[wid][lane * 8 + 4] = *(const float4*)(zp + lane * 8 + 4);
    __syncwarp();

    float S = g_sumz[n];
    int cnt = g_cnt[n];
    float dbest = 3.4e38f;
    int jbest = 0x7fffffff;

    if (cnt <= CAP) {
        for (int ci = lane; ci < cnt; ci += 32) {
            int j = g_cand[n][ci];
            const float* ep = emb + (size_t)j * CDIM;
            float g = 0.0f;
            for (int k = 0; k < CDIM; k += 8) {
                float4 e0 = *(const float4*)(ep + k);
                float4 e1 = *(const float4*)(ep + k + 4);
                g = fmaf(zrow[wid][k + 0], e0.x, g);
                g = fmaf(zrow[wid][k + 1], e0.y, g);
                g = fmaf(zrow[wid][k + 2], e0.z, g);
                g = fmaf(zrow[wid][k + 3], e0.w, g);
                g = fmaf(zrow[wid][k + 4], e1.x, g);
                g = fmaf(zrow[wid][k + 5], e1.y, g);
                g = fmaf(zrow[wid][k + 6], e1.z, g);
                g = fmaf(zrow[wid][k + 7], e1.w, g);
            }
            float d = __fadd_rn(fmaf(-2.0f, g, S), g_sume[j]);
            if (d < dbest || (d == dbest && j < jbest)) { dbest = d; jbest = j; }
        }
    } else {
        for (int j = lane; j < N_CODE; j += 32) {
            const float* ep = emb + (size_t)j * CDIM;
            float g = 0.0f;
            for (int k = 0; k < CDIM; k += 8) {
                float4 e0 = *(const float4*)(ep + k);
                float4 e1 = *(const float4*)(ep + k + 4);
                g = fmaf(zrow[wid][k + 0], e0.x, g);
                g = fmaf(zrow[wid][k + 1], e0.y, g);
                g = fmaf(zrow[wid][k + 2], e0.z, g);
                g = fmaf(zrow[wid][k + 3], e0.w, g);
                g = fmaf(zrow[wid][k + 4], e1.x, g);
                g = fmaf(zrow[wid][k + 5], e1.y, g);
                g = fmaf(zrow[wid][k + 6], e1.z, g);
                g = fmaf(zrow[wid][k + 7], e1.w, g);
            }
            float d = __fadd_rn(fmaf(-2.0f, g, S), g_sume[j]);
            if (d < dbest || (d == dbest && j < jbest)) { dbest = d; jbest = j; }
        }
    }
    #pragma unroll
    for (int off = 16; off; off >>= 1) {
        float d2 = __shfl_down_sync(0xffffffffu, dbest, off);
        int   j2 = __shfl_down_sync(0xffffffffu, jbest, off);
        if (d2 < dbest || (d2 == dbest && j2 < jbest)) { dbest = d2; jbest = j2; }
    }
    if (lane == 0) {
        g_idx[n] = jbest;
        atomicAdd(&g_counts[jbest], 1);
        if (write_idx) out_idx[n] = (float)jbest;
    }
}

// ============================================================
// K3: gather z_q, write z_q_st in [b,c,h,w], mse
// ============================================================
__global__ void k_output(const float* __restrict__ z, const float* __restrict__ emb,
                         float* __restrict__ out) {
    __shared__ float  tile[32][257];
    __shared__ double red[256];
    int bh = blockIdx.x;
    int b = bh >> 5, h = bh & 31;
    int tid = threadIdx.x;
    int base = bh * 32;

    for (int w = 0; w < 32; w++) {
        int idx = g_idx[base + w];
        tile[w][tid] = emb[(size_t)idx * CDIM + tid];
    }
    __syncthreads();

    int w = tid & 31, c0 = tid >> 5;
    const float* zb = z   + ((size_t)b * CDIM * HW + h) * HW;
    float*       ob = out + ((size_t)b * CDIM * HW + h) * HW;
    double macc = 0.0;
    #pragma unroll 4
    for (int cc = 0; cc < 32; cc++) {
        int c = c0 * 32 + cc;
        size_t off = (size_t)c * 1024 + w;
        float zv = zb[off];
        float q  = tile[w][c];
        float diff = __fsub_rn(q, zv);
        ob[off] = __fadd_rn(zv, diff);
        double e = (double)zv - (double)q;
        macc += e * e;
    }
    red[tid] = macc;
    __syncthreads();
    #pragma unroll
    for (int s = 128; s; s >>= 1) {
        if (tid < s) red[tid] += red[tid + s];
        __syncthreads();
    }
    if (tid == 0) atomicAdd(&g_mse, red[0]);
}

// ============================================================
// K4: scalars
// ============================================================
__global__ void k_scalars(float* __restrict__ out_scalars) {
    __shared__ double red[256];
    int tid = threadIdx.x;
    double s = 0.0;
    for (int j = tid; j < N_CODE; j += 256) {
        int c = g_counts[j];
        if (c > 0) {
            double p = (double)c / (double)N_TOK;
            s += p * log(p);
        }
    }
    red[tid] = s;
    __syncthreads();
    #pragma unroll
    for (int st = 128; st; st >>= 1) {
        if (tid < st) red[tid] += red[tid + st];
        __syncthreads();
    }
    if (tid == 0) {
        double loss = 1.25 * g_mse / (double)((size_t)N_TOK * CDIM);
        out_scalars[0] = (float)loss;
        out_scalars[1] = (float)exp(-red[0]);
    }
}

// ============================================================
extern "C" void kernel_launch(void* const* d_in, const int* in_sizes, int n_in,
                              void* d_out, int out_size) {
    const float* z   = (const float*)d_in[0];
    const float* emb = (const float*)d_in[1];
    float* out = (float*)d_out;

    int has_extra = (out_size >= (int)OUT_TOTAL) ? 1 : 0;

    cudaFuncSetAttribute(k_passA, cudaFuncAttributeMaxDynamicSharedMemorySize, SM_TOTAL);

    k_init<<<(N_CODE + 255) / 256, 256>>>(emb);
    k_conv_emb<<<(N_CODE * CDIM + 255) / 256, 256>>>(emb);
    k_transpose<<<1024, 256>>>(z);
    k_passA<<<N_TOK / 128, 256, SM_TOTAL>>>();
    k_passB<<<N_TOK / 8, 256>>>(emb, out + OUT_IDX, has_extra);
    k_output<<<1024, 256>>>(z, emb, out);
    if (has_extra) k_scalars<<<1, 256>>>(out + OUT_LOSS);
}

// round 6
// speedup vs baseline: 4.6058x; 1.0983x over previous
#include <cuda_runtime.h>
#include <cuda_bf16.h>
#include <math.h>
#include <stdint.h>

#define N_TOK   32768
#define N_CODE  8192
#define CDIM    256
#define HW      32

#define OUT_LOSS  8388608
#define OUT_PERP  8388609
#define OUT_IDX   8388610
#define OUT_TOTAL (8388608 + 2 + 32768)

#define CAP   48
#define EPS   1.5e-4f

// ---------------- device scratch (no allocation allowed) ----------------
__device__ float          g_zflat[N_TOK * CDIM];      // fp32 [token][c]
__device__ __nv_bfloat16  g_zf16[N_TOK * CDIM];       // bf16 tokens
__device__ __nv_bfloat16  g_ef16[N_CODE * CDIM];      // bf16 codebook
__device__ float          g_sumz[N_TOK];
__device__ float          g_sume[N_CODE];
__device__ int            g_idx[N_TOK];
__device__ int            g_counts[N_CODE];
__device__ int            g_cand[N_TOK][CAP];
__device__ int            g_cnt[N_TOK];
__device__ double         g_mse;

// ---------------- baseline-PTX helpers (NO sm_103a-only features) ----------------
__device__ __forceinline__ uint32_t smem_u32(const void* p) {
    uint32_t a;
    asm("{ .reg .u64 t; cvta.to.shared.u64 t, %1; cvt.u32.u64 %0, t; }" : "=r"(a) : "l"(p));
    return a;
}
#define CP_ASYNC(dst, src) asm volatile("cp.async.cg.shared.global [%0], [%1], 16;" :: "r"(dst), "l"(src))
#define CP_COMMIT()        asm volatile("cp.async.commit_group;" ::: "memory")
#define CP_WAIT1()         asm volatile("cp.async.wait_group 1;" ::: "memory")
#define CP_WAIT0()         asm volatile("cp.async.wait_group 0;" ::: "memory")

#define LDSM4(r, addr) \
    asm volatile("ldmatrix.sync.aligned.m8n8.x4.shared.b16 {%0,%1,%2,%3}, [%4];" \
        : "=r"((r)[0]), "=r"((r)[1]), "=r"((r)[2]), "=r"((r)[3]) : "r"(addr))

#define MMA_BF16(d, a, b0, b1) \
    asm volatile("mma.sync.aligned.m16n8k16.row.col.f32.bf16.bf16.f32 " \
        "{%0,%1,%2,%3}, {%4,%5,%6,%7}, {%8,%9}, {%0,%1,%2,%3};" \
        : "+f"((d)[0]), "+f"((d)[1]), "+f"((d)[2]), "+f"((d)[3]) \
        : "r"((a)[0]), "r"((a)[1]), "r"((a)[2]), "r"((a)[3]), "r"(b0), "r"(b1))

// ============================================================
// K0 (fused): bf16 codebook + ||e||^2 + zero counts/mse
// one warp per code row; 8 rows per 256-thread block
// ============================================================
__global__ void k_prep(const float* __restrict__ emb) {
    int wid = threadIdx.x >> 5, lane = threadIdx.x & 31;
    int j = blockIdx.x * 8 + wid;
    if (blockIdx.x == 0 && threadIdx.x == 0) g_mse = 0.0;
    if (threadIdx.x < 8) g_counts[blockIdx.x * 8 + threadIdx.x] = 0;

    const float* r = emb + (size_t)j * CDIM + lane * 8;
    float4 v0 = *(const float4*)r;
    float4 v1 = *(const float4*)(r + 4);
    double s = (double)v0.x * v0.x + (double)v0.y * v0.y +
               (double)v0.z * v0.z + (double)v0.w * v0.w +
               (double)v1.x * v1.x + (double)v1.y * v1.y +
               (double)v1.z * v1.z + (double)v1.w * v1.w;
    #pragma unroll
    for (int off = 16; off; off >>= 1) s += __shfl_down_sync(0xffffffffu, s, off);
    if (lane == 0) g_sume[j] = (float)s;

    __nv_bfloat16 b[8];
    b[0] = __float2bfloat16(v0.x); b[1] = __float2bfloat16(v0.y);
    b[2] = __float2bfloat16(v0.z); b[3] = __float2bfloat16(v0.w);
    b[4] = __float2bfloat16(v1.x); b[5] = __float2bfloat16(v1.y);
    b[6] = __float2bfloat16(v1.z); b[7] = __float2bfloat16(v1.w);
    *(uint4*)(g_ef16 + (size_t)j * CDIM + lane * 8) = *(uint4*)b;
}

// ============================================================
// K1: transpose z -> z_flat (fp32 + bf16) + sumz
// ============================================================
__global__ void k_transpose(const float* __restrict__ z) {
    __shared__ float  tile[32][257];
    __shared__ double red[8][32];
    int bh = blockIdx.x;
    int b = bh >> 5, h = bh & 31;
    int tid = threadIdx.x;
    int w = tid & 31, c0 = tid >> 5;

    const float* zb = z + ((size_t)b * CDIM * HW + h) * HW;
    double pd = 0.0;
    #pragma unroll 4
    for (int cc = 0; cc < 32; cc++) {
        int c = c0 * 32 + cc;
        float v = zb[(size_t)c * 1024 + w];
        tile[w][c] = v;
        pd += (double)v * (double)v;
    }
    red[c0][w] = pd;
    __syncthreads();

    int base = bh * 32;
    if (tid < 32) {
        double s = 0.0;
        #pragma unroll
        for (int g = 0; g < 8; g++) s += red[g][tid];
        g_sumz[base + tid] = (float)s;
    }
    #pragma unroll 4
    for (int w2 = 0; w2 < 32; w2++) {
        float v = tile[w2][tid];
        size_t o = (size_t)(base + w2) * CDIM + tid;
        g_zflat[o] = v;
        g_zf16[o]  = __float2bfloat16(v);
    }
}

// ============================================================
// Pass A: bf16 mma.sync GEMM + streaming min + candidate capture
// CTA = 128 tokens x 8192 codes (64 tiles of 128 codes)
// 512 threads, 16 warps in 4(m) x 4(n), warp tile 32x32, m16n8k16
// SMEM: A[128][256] resident (64KB) + B double buffer (2x64KB) + scnt
// ============================================================
#define SM_A      0
#define SM_B0     65536
#define SM_B1     131072
#define SM_CNT    196608
#define SM_TOTAL  (196608 + 512)
#define NTHREADS  512

__device__ __forceinline__ void load_B_tile(int t, uint32_t base, int tid) {
    const __nv_bfloat16* ep = g_ef16 + (size_t)t * 128 * CDIM;
    #pragma unroll
    for (int it = 0; it < 8; it++) {
        int idx = tid + it * NTHREADS;
        int r = idx >> 5, c = idx & 31;
        uint32_t dst = base + (uint32_t)r * 512u + (uint32_t)((c ^ (r & 7)) * 16);
        CP_ASYNC(dst, (const void*)(ep + (size_t)r * CDIM + c * 8));
    }
}

__global__ void __launch_bounds__(NTHREADS, 1) k_passA() {
    extern __shared__ char smem[];
    const uint32_t sb = smem_u32(smem);
    int* scnt = (int*)(smem + SM_CNT);
    int tid = threadIdx.x, lane = tid & 31, wid = tid >> 5;
    int warp_m = wid >> 2, warp_n = wid & 3;
    int m0 = blockIdx.x * 128;

    if (tid < 128) scnt[tid] = 0;

    // stage whole A tile (128 tokens x 256) into swizzled SMEM
    {
        const __nv_bfloat16* za = g_zf16 + (size_t)m0 * CDIM;
        #pragma unroll
        for (int it = 0; it < 8; it++) {
            int idx = tid + it * NTHREADS;
            int r = idx >> 5, c = idx & 31;
            uint32_t dst = sb + SM_A + (uint32_t)r * 512u + (uint32_t)((c ^ (r & 7)) * 16);
            CP_ASYNC(dst, (const void*)(za + (size_t)r * CDIM + c * 8));
        }
    }
    CP_COMMIT();
    load_B_tile(0, sb + SM_B0, tid);
    CP_COMMIT();

    // per-thread A-row addressing (fixed across tiles): 2 m-blocks of 16
    uint32_t a_row[2]; int a_rl[2];
    #pragma unroll
    for (int mi = 0; mi < 2; mi++) {
        int row = warp_m * 32 + mi * 16 + (lane & 15);
        a_row[mi] = sb + SM_A + (uint32_t)row * 512u;
        a_rl[mi] = row & 7;
    }
    int a_hi = (lane >> 4) & 1;
    int q = lane >> 3;
    int b_hi = q & 1;
    int b_rowoff[2]; int b_rl[2];
    #pragma unroll
    for (int p = 0; p < 2; p++) {
        int row = warp_n * 32 + p * 16 + ((q & 2) << 2) + (lane & 7);
        b_rowoff[p] = row * 512;
        b_rl[p] = row & 7;
    }

    float bd[4];
    #pragma unroll
    for (int i = 0; i < 4; i++) bd[i] = 3.4e38f;

    for (int t = 0; t < 64; t++) {
        uint32_t bbuf = sb + ((t & 1) ? SM_B1 : SM_B0);
        if (t + 1 < 64) {
            load_B_tile(t + 1, sb + ((t & 1) ? SM_B0 : SM_B1), tid);
            CP_COMMIT();
            CP_WAIT1();
        } else {
            CP_WAIT0();
        }
        __syncthreads();

        float acc[2][4][4];
        #pragma unroll
        for (int mi = 0; mi < 2; mi++)
            #pragma unroll
            for (int ni = 0; ni < 4; ni++)
                #pragma unroll
                for (int e = 0; e < 4; e++) acc[mi][ni][e] = 0.0f;

        #pragma unroll 4
        for (int ks = 0; ks < 16; ks++) {
            uint32_t a[2][4], b[2][4];
            #pragma unroll
            for (int mi = 0; mi < 2; mi++) {
                uint32_t addr = a_row[mi] + (uint32_t)((((ks * 2 + a_hi) ^ a_rl[mi])) * 16);
                LDSM4(a[mi], addr);
            }
            #pragma unroll
            for (int p = 0; p < 2; p++) {
                uint32_t addr = bbuf + (uint32_t)b_rowoff[p] + (uint32_t)((((ks * 2 + b_hi) ^ b_rl[p])) * 16);
                LDSM4(b[p], addr);
            }
            #pragma unroll
            for (int mi = 0; mi < 2; mi++) {
                MMA_BF16(acc[mi][0], a[mi], b[0][0], b[0][1]);
                MMA_BF16(acc[mi][1], a[mi], b[0][2], b[0][3]);
                MMA_BF16(acc[mi][2], a[mi], b[1][0], b[1][1]);
                MMA_BF16(acc[mi][3], a[mi], b[1][2], b[1][3]);
            }
        }

        // ---- epilogue: scores, running min, candidate capture ----
        float se[4][2];
        int colbase = t * 128 + warp_n * 32 + 2 * (lane & 3);
        #pragma unroll
        for (int ni = 0; ni < 4; ni++) {
            se[ni][0] = __ldg(&g_sume[colbase + ni * 8]);
            se[ni][1] = __ldg(&g_sume[colbase + ni * 8 + 1]);
        }
        #pragma unroll
        for (int mi = 0; mi < 2; mi++) {
            #pragma unroll
            for (int half = 0; half < 2; half++) {
                float s[8];
                #pragma unroll
                for (int ni = 0; ni < 4; ni++) {
                    s[ni * 2 + 0] = fmaf(-2.0f, acc[mi][ni][half * 2 + 0], se[ni][0]);
                    s[ni * 2 + 1] = fmaf(-2.0f, acc[mi][ni][half * 2 + 1], se[ni][1]);
                }
                float lmin = s[0];
                #pragma unroll
                for (int v = 1; v < 8; v++) lmin = fminf(lmin, s[v]);
                lmin = fminf(lmin, __shfl_xor_sync(0xffffffffu, lmin, 1));
                lmin = fminf(lmin, __shfl_xor_sync(0xffffffffu, lmin, 2));
                int bi = mi * 2 + half;
                float nm = fminf(bd[bi], lmin);
                if (lmin < bd[bi] + EPS) {
                    int r_local = warp_m * 32 + mi * 16 + half * 8 + (lane >> 2);
                    #pragma unroll
                    for (int v = 0; v < 8; v++) {
                        if (s[v] < nm + EPS) {
                            int pos = atomicAdd(&scnt[r_local], 1);
                            if (pos < CAP)
                                g_cand[m0 + r_local][pos] = colbase + (v >> 1) * 8 + (v & 1);
                        }
                    }
                }
                bd[bi] = nm;
            }
        }
        __syncthreads();
    }

    if (tid < 128) g_cnt[m0 + tid] = scnt[tid];
}

// ============================================================
// Pass B: exact fp32 (reference-rounded) re-argmin over candidates
// ============================================================
__global__ void __launch_bounds__(256) k_passB(const float* __restrict__ emb,
                                               float* __restrict__ out_idx, int write_idx) {
    __shared__ float zrow[8][CDIM];
    int wid = threadIdx.x >> 5, lane = threadIdx.x & 31;
    int n = blockIdx.x * 8 + wid;

    const float* zp = g_zflat + (size_t)n * CDIM;
    *(float4*)&zrow[wid][lane * 8]     = *(const float4*)(zp + lane * 8);
    *(float4*)&zrow[wid][lane * 8 + 4] = *(const float4*)(zp + lane * 8 + 4);
    __syncwarp();

    float S = g_sumz[n];
    int cnt = g_cnt[n];
    float dbest = 3.4e38f;
    int jbest = 0x7fffffff;

    if (cnt <= CAP) {
        for (int ci = lane; ci < cnt; ci += 32) {
            int j = g_cand[n][ci];
            const float* ep = emb + (size_t)j * CDIM;
            float g = 0.0f;
            for (int k = 0; k < CDIM; k += 8) {
                float4 e0 = *(const float4*)(ep + k);
                float4 e1 = *(const float4*)(ep + k + 4);
                g = fmaf(zrow[wid][k + 0], e0.x, g);
                g = fmaf(zrow[wid][k + 1], e0.y, g);
                g = fmaf(zrow[wid][k + 2], e0.z, g);
                g = fmaf(zrow[wid][k + 3], e0.w, g);
                g = fmaf(zrow[wid][k + 4], e1.x, g);
                g = fmaf(zrow[wid][k + 5], e1.y, g);
                g = fmaf(zrow[wid][k + 6], e1.z, g);
                g = fmaf(zrow[wid][k + 7], e1.w, g);
            }
            float d = __fadd_rn(fmaf(-2.0f, g, S), g_sume[j]);
            if (d < dbest || (d == dbest && j < jbest)) { dbest = d; jbest = j; }
        }
    } else {
        for (int j = lane; j < N_CODE; j += 32) {
            const float* ep = emb + (size_t)j * CDIM;
            float g = 0.0f;
            for (int k = 0; k < CDIM; k += 8) {
                float4 e0 = *(const float4*)(ep + k);
                float4 e1 = *(const float4*)(ep + k + 4);
                g = fmaf(zrow[wid][k + 0], e0.x, g);
                g = fmaf(zrow[wid][k + 1], e0.y, g);
                g = fmaf(zrow[wid][k + 2], e0.z, g);
                g = fmaf(zrow[wid][k + 3], e0.w, g);
                g = fmaf(zrow[wid][k + 4], e1.x, g);
                g = fmaf(zrow[wid][k + 5], e1.y, g);
                g = fmaf(zrow[wid][k + 6], e1.z, g);
                g = fmaf(zrow[wid][k + 7], e1.w, g);
            }
            float d = __fadd_rn(fmaf(-2.0f, g, S), g_sume[j]);
            if (d < dbest || (d == dbest && j < jbest)) { dbest = d; jbest = j; }
        }
    }
    #pragma unroll
    for (int off = 16; off; off >>= 1) {
        float d2 = __shfl_down_sync(0xffffffffu, dbest, off);
        int   j2 = __shfl_down_sync(0xffffffffu, jbest, off);
        if (d2 < dbest || (d2 == dbest && j2 < jbest)) { dbest = d2; jbest = j2; }
    }
    if (lane == 0) {
        g_idx[n] = jbest;
        atomicAdd(&g_counts[jbest], 1);
        if (write_idx) out_idx[n] = (float)jbest;
    }
}

// ============================================================
// K3: gather z_q, write z_q_st in [b,c,h,w], mse
// ============================================================
__global__ void k_output(const float* __restrict__ z, const float* __restrict__ emb,
                         float* __restrict__ out) {
    __shared__ float  tile[32][257];
    __shared__ double red[256];
    int bh = blockIdx.x;
    int b = bh >> 5, h = bh & 31;
    int tid = threadIdx.x;
    int base = bh * 32;

    for (int w = 0; w < 32; w++) {
        int idx = g_idx[base + w];
        tile[w][tid] = emb[(size_t)idx * CDIM + tid];
    }
    __syncthreads();

    int w = tid & 31, c0 = tid >> 5;
    const float* zb = z   + ((size_t)b * CDIM * HW + h) * HW;
    float*       ob = out + ((size_t)b * CDIM * HW + h) * HW;
    double macc = 0.0;
    #pragma unroll 4
    for (int cc = 0; cc < 32; cc++) {
        int c = c0 * 32 + cc;
        size_t off = (size_t)c * 1024 + w;
        float zv = zb[off];
        float q  = tile[w][c];
        float diff = __fsub_rn(q, zv);
        ob[off] = __fadd_rn(zv, diff);
        double e = (double)zv - (double)q;
        macc += e * e;
    }
    red[tid] = macc;
    __syncthreads();
    #pragma unroll
    for (int s = 128; s; s >>= 1) {
        if (tid < s) red[tid] += red[tid + s];
        __syncthreads();
    }
    if (tid == 0) atomicAdd(&g_mse, red[0]);
}

// ============================================================
// K4: scalars
// ============================================================
__global__ void k_scalars(float* __restrict__ out_scalars) {
    __shared__ double red[256];
    int tid = threadIdx.x;
    double s = 0.0;
    for (int j = tid; j < N_CODE; j += 256) {
        int c = g_counts[j];
        if (c > 0) {
            double p = (double)c / (double)N_TOK;
            s += p * log(p);
        }
    }
    red[tid] = s;
    __syncthreads();
    #pragma unroll
    for (int st = 128; st; st >>= 1) {
        if (tid < st) red[tid] += red[tid + st];
        __syncthreads();
    }
    if (tid == 0) {
        double loss = 1.25 * g_mse / (double)((size_t)N_TOK * CDIM);
        out_scalars[0] = (float)loss;
        out_scalars[1] = (float)exp(-red[0]);
    }
}

// ============================================================
extern "C" void kernel_launch(void* const* d_in, const int* in_sizes, int n_in,
                              void* d_out, int out_size) {
    const float* z   = (const float*)d_in[0];
    const float* emb = (const float*)d_in[1];
    float* out = (float*)d_out;

    int has_extra = (out_size >= (int)OUT_TOTAL) ? 1 : 0;

    cudaFuncSetAttribute(k_passA, cudaFuncAttributeMaxDynamicSharedMemorySize, SM_TOTAL);

    k_prep<<<N_CODE / 8, 256>>>(emb);
    k_transpose<<<1024, 256>>>(z);
    k_passA<<<N_TOK / 128, NTHREADS, SM_TOTAL>>>();
    k_passB<<<N_TOK / 8, 256>>>(emb, out + OUT_IDX, has_extra);
    k_output<<<1024, 256>>>(z, emb, out);
    if (has_extra) k_scalars<<<1, 256>>>(out + OUT_LOSS);
}

// round 8
// speedup vs baseline: 4.7477x; 1.0308x over previous
#include <cuda_runtime.h>
#include <cuda_bf16.h>
#include <math.h>
#include <stdint.h>

#define N_TOK   32768
#define N_CODE  8192
#define CDIM    256
#define HW      32

#define OUT_LOSS  8388608
#define OUT_PERP  8388609
#define OUT_IDX   8388610
#define OUT_TOTAL (8388608 + 2 + 32768)

#define CAP   48
#define EPS   7e-5f

// ---------------- device scratch (no allocation allowed) ----------------
__device__ float          g_zflat[N_TOK * CDIM];      // fp32 [token][c]
__device__ __nv_bfloat16  g_zf16[N_TOK * CDIM];       // bf16 tokens
__device__ __nv_bfloat16  g_ef16[N_CODE * CDIM];      // bf16 codebook
__device__ float          g_sumz[N_TOK];
__device__ float          g_sume[N_CODE];
__device__ int            g_idx[N_TOK];
__device__ int            g_counts[N_CODE];
__device__ int            g_cand[N_TOK][CAP];
__device__ int            g_cnt[N_TOK];
__device__ double         g_mse;

// ---------------- baseline-PTX helpers (NO sm_103a-only features) ----------------
__device__ __forceinline__ uint32_t smem_u32(const void* p) {
    uint32_t a;
    asm("{ .reg .u64 t; cvta.to.shared.u64 t, %1; cvt.u32.u64 %0, t; }" : "=r"(a) : "l"(p));
    return a;
}
#define CP_ASYNC(dst, src) asm volatile("cp.async.cg.shared.global [%0], [%1], 16;" :: "r"(dst), "l"(src))
#define CP_COMMIT()        asm volatile("cp.async.commit_group;" ::: "memory")
#define CP_WAIT1()         asm volatile("cp.async.wait_group 1;" ::: "memory")
#define CP_WAIT0()         asm volatile("cp.async.wait_group 0;" ::: "memory")

#define LDSM4(r, addr) \
    asm volatile("ldmatrix.sync.aligned.m8n8.x4.shared.b16 {%0,%1,%2,%3}, [%4];" \
        : "=r"((r)[0]), "=r"((r)[1]), "=r"((r)[2]), "=r"((r)[3]) : "r"(addr))

#define MMA_BF16(d, a, b0, b1) \
    asm volatile("mma.sync.aligned.m16n8k16.row.col.f32.bf16.bf16.f32 " \
        "{%0,%1,%2,%3}, {%4,%5,%6,%7}, {%8,%9}, {%0,%1,%2,%3};" \
        : "+f"((d)[0]), "+f"((d)[1]), "+f"((d)[2]), "+f"((d)[3]) \
        : "r"((a)[0]), "r"((a)[1]), "r"((a)[2]), "r"((a)[3]), "r"(b0), "r"(b1))

// ============================================================
// K0 (fused): bf16 codebook + ||e||^2 + zero counts/mse
// ============================================================
__global__ void k_prep(const float* __restrict__ emb) {
    int wid = threadIdx.x >> 5, lane = threadIdx.x & 31;
    int j = blockIdx.x * 8 + wid;
    if (blockIdx.x == 0 && threadIdx.x == 0) g_mse = 0.0;
    if (threadIdx.x < 8) g_counts[blockIdx.x * 8 + threadIdx.x] = 0;

    const float* r = emb + (size_t)j * CDIM + lane * 8;
    float4 v0 = *(const float4*)r;
    float4 v1 = *(const float4*)(r + 4);
    double s = (double)v0.x * v0.x + (double)v0.y * v0.y +
               (double)v0.z * v0.z + (double)v0.w * v0.w +
               (double)v1.x * v1.x + (double)v1.y * v1.y +
               (double)v1.z * v1.z + (double)v1.w * v1.w;
    #pragma unroll
    for (int off = 16; off; off >>= 1) s += __shfl_down_sync(0xffffffffu, s, off);
    if (lane == 0) g_sume[j] = (float)s;

    __nv_bfloat16 b[8];
    b[0] = __float2bfloat16(v0.x); b[1] = __float2bfloat16(v0.y);
    b[2] = __float2bfloat16(v0.z); b[3] = __float2bfloat16(v0.w);
    b[4] = __float2bfloat16(v1.x); b[5] = __float2bfloat16(v1.y);
    b[6] = __float2bfloat16(v1.z); b[7] = __float2bfloat16(v1.w);
    *(uint4*)(g_ef16 + (size_t)j * CDIM + lane * 8) = *(uint4*)b;
}

// ============================================================
// K1: transpose z -> z_flat (fp32 + bf16) + sumz
// ============================================================
__global__ void k_transpose(const float* __restrict__ z) {
    __shared__ float  tile[32][257];
    __shared__ double red[8][32];
    int bh = blockIdx.x;
    int b = bh >> 5, h = bh & 31;
    int tid = threadIdx.x;
    int w = tid & 31, c0 = tid >> 5;

    const float* zb = z + ((size_t)b * CDIM * HW + h) * HW;
    double pd = 0.0;
    #pragma unroll 4
    for (int cc = 0; cc < 32; cc++) {
        int c = c0 * 32 + cc;
        float v = zb[(size_t)c * 1024 + w];
        tile[w][c] = v;
        pd += (double)v * (double)v;
    }
    red[c0][w] = pd;
    __syncthreads();

    int base = bh * 32;
    if (tid < 32) {
        double s = 0.0;
        #pragma unroll
        for (int g = 0; g < 8; g++) s += red[g][tid];
        g_sumz[base + tid] = (float)s;
    }
    #pragma unroll 4
    for (int w2 = 0; w2 < 32; w2++) {
        float v = tile[w2][tid];
        size_t o = (size_t)(base + w2) * CDIM + tid;
        g_zflat[o] = v;
        g_zf16[o]  = __float2bfloat16(v);
    }
}

// ============================================================
// Pass A: bf16 mma.sync GEMM + streaming min + candidate capture
// CTA = 128 tokens x 8192 codes (64 tiles of 128 codes)
// 512 threads, 16 warps in 4(m) x 4(n), warp tile 32x32, m16n8k16
// k-loop fragments explicitly double-buffered (LDSM ks+1 || MMA ks)
// ============================================================
#define SM_A      0
#define SM_B0     65536
#define SM_B1     131072
#define SM_CNT    196608
#define SM_TOTAL  (196608 + 512)
#define NTHREADS  512

__device__ __forceinline__ void load_B_tile(int t, uint32_t base, int tid) {
    const __nv_bfloat16* ep = g_ef16 + (size_t)t * 128 * CDIM;
    #pragma unroll
    for (int it = 0; it < 8; it++) {
        int idx = tid + it * NTHREADS;
        int r = idx >> 5, c = idx & 31;
        uint32_t dst = base + (uint32_t)r * 512u + (uint32_t)((c ^ (r & 7)) * 16);
        CP_ASYNC(dst, (const void*)(ep + (size_t)r * CDIM + c * 8));
    }
}

#define LOAD_FRAGS(slot, kss) do {                                                   \
    uint32_t _ad0 = a_row[0] + (uint32_t)(((((kss) * 2 + a_hi)) ^ a_rl[0]) * 16);    \
    LDSM4(af[slot][0], _ad0);                                                        \
    uint32_t _ad1 = a_row[1] + (uint32_t)(((((kss) * 2 + a_hi)) ^ a_rl[1]) * 16);    \
    LDSM4(af[slot][1], _ad1);                                                        \
    uint32_t _bd0 = bbuf + (uint32_t)b_rowoff[0] + (uint32_t)(((((kss) * 2 + b_hi)) ^ b_rl[0]) * 16); \
    LDSM4(bf[slot][0], _bd0);                                                        \
    uint32_t _bd1 = bbuf + (uint32_t)b_rowoff[1] + (uint32_t)(((((kss) * 2 + b_hi)) ^ b_rl[1]) * 16); \
    LDSM4(bf[slot][1], _bd1);                                                        \
} while (0)

__global__ void __launch_bounds__(NTHREADS, 1) k_passA() {
    extern __shared__ char smem[];
    const uint32_t sb = smem_u32(smem);
    int* scnt = (int*)(smem + SM_CNT);
    int tid = threadIdx.x, lane = tid & 31, wid = tid >> 5;
    int warp_m = wid >> 2, warp_n = wid & 3;
    int m0 = blockIdx.x * 128;

    if (tid < 128) scnt[tid] = 0;

    // stage whole A tile (128 tokens x 256) into swizzled SMEM
    {
        const __nv_bfloat16* za = g_zf16 + (size_t)m0 * CDIM;
        #pragma unroll
        for (int it = 0; it < 8; it++) {
            int idx = tid + it * NTHREADS;
            int r = idx >> 5, c = idx & 31;
            uint32_t dst = sb + SM_A + (uint32_t)r * 512u + (uint32_t)((c ^ (r & 7)) * 16);
            CP_ASYNC(dst, (const void*)(za + (size_t)r * CDIM + c * 8));
        }
    }
    CP_COMMIT();
    load_B_tile(0, sb + SM_B0, tid);
    CP_COMMIT();

    uint32_t a_row[2]; int a_rl[2];
    #pragma unroll
    for (int mi = 0; mi < 2; mi++) {
        int row = warp_m * 32 + mi * 16 + (lane & 15);
        a_row[mi] = sb + SM_A + (uint32_t)row * 512u;
        a_rl[mi] = row & 7;
    }
    int a_hi = (lane >> 4) & 1;
    int q = lane >> 3;
    int b_hi = q & 1;
    int b_rowoff[2]; int b_rl[2];
    #pragma unroll
    for (int p = 0; p < 2; p++) {
        int row = warp_n * 32 + p * 16 + ((q & 2) << 2) + (lane & 7);
        b_rowoff[p] = row * 512;
        b_rl[p] = row & 7;
    }

    float bd[4];
    #pragma unroll
    for (int i = 0; i < 4; i++) bd[i] = 3.4e38f;

    for (int t = 0; t < 64; t++) {
        uint32_t bbuf = sb + ((t & 1) ? SM_B1 : SM_B0);
        if (t + 1 < 64) {
            load_B_tile(t + 1, sb + ((t & 1) ? SM_B0 : SM_B1), tid);
            CP_COMMIT();
            CP_WAIT1();
        } else {
            CP_WAIT0();
        }
        __syncthreads();

        float acc[2][4][4];
        #pragma unroll
        for (int mi = 0; mi < 2; mi++)
            #pragma unroll
            for (int ni = 0; ni < 4; ni++)
                #pragma unroll
                for (int e = 0; e < 4; e++) acc[mi][ni][e] = 0.0f;

        // software-pipelined k-loop: frags double-buffered in regs
        uint32_t af[2][2][4], bf[2][2][4];
        LOAD_FRAGS(0, 0);
        #pragma unroll
        for (int ks = 0; ks < 16; ks++) {
            int cur = ks & 1, nxt = cur ^ 1;
            if (ks < 15) LOAD_FRAGS(nxt, ks + 1);
            #pragma unroll
            for (int mi = 0; mi < 2; mi++) {
                MMA_BF16(acc[mi][0], af[cur][mi], bf[cur][0][0], bf[cur][0][1]);
                MMA_BF16(acc[mi][1], af[cur][mi], bf[cur][0][2], bf[cur][0][3]);
                MMA_BF16(acc[mi][2], af[cur][mi], bf[cur][1][0], bf[cur][1][1]);
                MMA_BF16(acc[mi][3], af[cur][mi], bf[cur][1][2], bf[cur][1][3]);
            }
        }

        // ---- epilogue: scores, running min, candidate capture ----
        float se[4][2];
        int colbase = t * 128 + warp_n * 32 + 2 * (lane & 3);
        #pragma unroll
        for (int ni = 0; ni < 4; ni++) {
            se[ni][0] = __ldg(&g_sume[colbase + ni * 8]);
            se[ni][1] = __ldg(&g_sume[colbase + ni * 8 + 1]);
        }
        #pragma unroll
        for (int mi = 0; mi < 2; mi++) {
            #pragma unroll
            for (int half = 0; half < 2; half++) {
                float s[8];
                #pragma unroll
                for (int ni = 0; ni < 4; ni++) {
                    s[ni * 2 + 0] = fmaf(-2.0f, acc[mi][ni][half * 2 + 0], se[ni][0]);
                    s[ni * 2 + 1] = fmaf(-2.0f, acc[mi][ni][half * 2 + 1], se[ni][1]);
                }
                float lmin = s[0];
                #pragma unroll
                for (int v = 1; v < 8; v++) lmin = fminf(lmin, s[v]);
                lmin = fminf(lmin, __shfl_xor_sync(0xffffffffu, lmin, 1));
                lmin = fminf(lmin, __shfl_xor_sync(0xffffffffu, lmin, 2));
                int bi = mi * 2 + half;
                float nm = fminf(bd[bi], lmin);
                if (lmin < bd[bi] + EPS) {
                    int r_local = warp_m * 32 + mi * 16 + half * 8 + (lane >> 2);
                    #pragma unroll
                    for (int v = 0; v < 8; v++) {
                        if (s[v] < nm + EPS) {
                            int pos = atomicAdd(&scnt[r_local], 1);
                            if (pos < CAP)
                                g_cand[m0 + r_local][pos] = colbase + (v >> 1) * 8 + (v & 1);
                        }
                    }
                }
                bd[bi] = nm;
            }
        }
        __syncthreads();
    }

    if (tid < 128) g_cnt[m0 + tid] = scnt[tid];
}

// ============================================================
// Pass B: exact fp32 (reference-rounded) re-argmin over candidates
// ============================================================
__global__ void __launch_bounds__(256) k_passB(const float* __restrict__ emb,
                                               float* __restrict__ out_idx, int write_idx) {
    __shared__ float zrow[8][CDIM];
    int wid = threadIdx.x >> 5, lane = threadIdx.x & 31;
    int n = blockIdx.x * 8 + wid;

    const float* zp = g_zflat + (size_t)n * CDIM;
    *(float4*)&zrow[wid][lane * 8]     = *(const float4*)(zp + lane * 8);
    *(float4*)&zrow[wid][lane * 8 + 4] = *(const float4*)(zp + lane * 8 + 4);
    __syncwarp();

    float S = g_sumz[n];
    int cnt = g_cnt[n];
    float dbest = 3.4e38f;
    int jbest = 0x7fffffff;

    if (cnt <= CAP) {
        for (int ci = lane; ci < cnt; ci += 32) {
            int j = g_cand[n][ci];
            const float* ep = emb + (size_t)j * CDIM;
            float g = 0.0f;
            for (int k = 0; k < CDIM; k += 8) {
                float4 e0 = *(const float4*)(ep + k);
                float4 e1 = *(const float4*)(ep + k + 4);
                g = fmaf(zrow[wid][k + 0], e0.x, g);
                g = fmaf(zrow[wid][k + 1], e0.y, g);
                g = fmaf(zrow[wid][k + 2], e0.z, g);
                g = fmaf(zrow[wid][k + 3], e0.w, g);
                g = fmaf(zrow[wid][k + 4], e1.x, g);
                g = fmaf(zrow[wid][k + 5], e1.y, g);
                g = fmaf(zrow[wid][k + 6], e1.z, g);
                g = fmaf(zrow[wid][k + 7], e1.w, g);
            }
            float d = __fadd_rn(fmaf(-2.0f, g, S), g_sume[j]);
            if (d < dbest || (d == dbest && j < jbest)) { dbest = d; jbest = j; }
        }
    } else {
        for (int j = lane; j < N_CODE; j += 32) {
            const float* ep = emb + (size_t)j * CDIM;
            float g = 0.0f;
            for (int k = 0; k < CDIM; k += 8) {
                float4 e0 = *(const float4*)(ep + k);
                float4 e1 = *(const float4*)(ep + k + 4);
                g = fmaf(zrow[wid][k + 0], e0.x, g);
                g = fmaf(zrow[wid][k + 1], e0.y, g);
                g = fmaf(zrow[wid][k + 2], e0.z, g);
                g = fmaf(zrow[wid][k + 3], e0.w, g);
                g = fmaf(zrow[wid][k + 4], e1.x, g);
                g = fmaf(zrow[wid][k + 5], e1.y, g);
                g = fmaf(zrow[wid][k + 6], e1.z, g);
                g = fmaf(zrow[wid][k + 7], e1.w, g);
            }
            float d = __fadd_rn(fmaf(-2.0f, g, S), g_sume[j]);
            if (d < dbest || (d == dbest && j < jbest)) { dbest = d; jbest = j; }
        }
    }
    #pragma unroll
    for (int off = 16; off; off >>= 1) {
        float d2 = __shfl_down_sync(0xffffffffu, dbest, off);
        int   j2 = __shfl_down_sync(0xffffffffu, jbest, off);
        if (d2 < dbest || (d2 == dbest && j2 < jbest)) { dbest = d2; jbest = j2; }
    }
    if (lane == 0) {
        g_idx[n] = jbest;
        atomicAdd(&g_counts[jbest], 1);
        if (write_idx) out_idx[n] = (float)jbest;
    }
}

// ============================================================
// K3: gather z_q, write z_q_st in [b,c,h,w], mse
// ============================================================
__global__ void k_output(const float* __restrict__ z, const float* __restrict__ emb,
                         float* __restrict__ out) {
    __shared__ float  tile[32][257];
    __shared__ double red[256];
    int bh = blockIdx.x;
    int b = bh >> 5, h = bh & 31;
    int tid = threadIdx.x;
    int base = bh * 32;

    for (int w = 0; w < 32; w++) {
        int idx = g_idx[base + w];
        tile[w][tid] = emb[(size_t)idx * CDIM + tid];
    }
    __syncthreads();

    int w = tid & 31, c0 = tid >> 5;
    const float* zb = z   + ((size_t)b * CDIM * HW + h) * HW;
    float*       ob = out + ((size_t)b * CDIM * HW + h) * HW;
    double macc = 0.0;
    #pragma unroll 4
    for (int cc = 0; cc < 32; cc++) {
        int c = c0 * 32 + cc;
        size_t off = (size_t)c * 1024 + w;
        float zv = zb[off];
        float q  = tile[w][c];
        float diff = __fsub_rn(q, zv);
        ob[off] = __fadd_rn(zv, diff);
        double e = (double)zv - (double)q;
        macc += e * e;
    }
    red[tid] = macc;
    __syncthreads();
    #pragma unroll
    for (int s = 128; s; s >>= 1) {
        if (tid < s) red[tid] += red[tid + s];
        __syncthreads();
    }
    if (tid == 0) atomicAdd(&g_mse, red[0]);
}

// ============================================================
// K4: scalars
// ============================================================
__global__ void k_scalars(float* __restrict__ out_scalars) {
    __shared__ double red[256];
    int tid = threadIdx.x;
    double s = 0.0;
    for (int j = tid; j < N_CODE; j += 256) {
        int c = g_counts[j];
        if (c > 0) {
            double p = (double)c / (double)N_TOK;
            s += p * log(p);
        }
    }
    red[tid] = s;
    __syncthreads();
    #pragma unroll
    for (int st = 128; st; st >>= 1) {
        if (tid < st) red[tid] += red[tid + st];
        __syncthreads();
    }
    if (tid == 0) {
        double loss = 1.25 * g_mse / (double)((size_t)N_TOK * CDIM);
        out_scalars[0] = (float)loss;
        out_scalars[1] = (float)exp(-red[0]);
    }
}

// ============================================================
extern "C" void kernel_launch(void* const* d_in, const int* in_sizes, int n_in,
                              void* d_out, int out_size) {
    const float* z   = (const float*)d_in[0];
    const float* emb = (const float*)d_in[1];
    float* out = (float*)d_out;

    int has_extra = (out_size >= (int)OUT_TOTAL) ? 1 : 0;

    cudaFuncSetAttribute(k_passA, cudaFuncAttributeMaxDynamicSharedMemorySize, SM_TOTAL);

    k_prep<<<N_CODE / 8, 256>>>(emb);
    k_transpose<<<1024, 256>>>(z);
    k_passA<<<N_TOK / 128, NTHREADS, SM_TOTAL>>>();
    k_passB<<<N_TOK / 8, 256>>>(emb, out + OUT_IDX, has_extra);
    k_output<<<1024, 256>>>(z, emb, out);
    if (has_extra) k_scalars<<<1, 256>>>(out + OUT_LOSS);
}